// round 15
// baseline (speedup 1.0000x reference)
#include <cuda_runtime.h>
#include <cstdint>

// GaussianPooling: out[n,c] = sum_{dy,dx} fm[c, y+dy, x+dx] * kern[dy,dx]
// fm: [512,256,256] f32, keypoints: [4096,2] int (x,y), out: [4096,512] f32.
// Separable 5x5 Gaussian (sigma=2).
//
// SINGLE fused kernel. block = (stripe of 32 rows, channel pair), 3/SM:
//   - issue 72x cp.async.bulk row copies (TMA engine)
//   - while fetch is in flight: scan ALL keypoints (16/thread, coalesced,
//     L2-hot) into 8 packed registers
//   - mbarrier wait; sync-free in-place vertical conv (rolling 5-reg window)
//   - compact this stripe's matches into a smem queue overlaid on the dead
//     halo rows (ballot-aggregated atomics)
//   - block-wide gather: 2 LDS.128 per kp per channel, STG.64 out
// First-wave fetch stagger (2us steps) de-phase-locks DRAM bursts.

#define C_DIM 512
#define H_DIM 256
#define W_DIM 256
#define N_KP  4096
#define PLANE (H_DIM * W_DIM)
#define STRIPE_ROWS 32
#define N_STRIPES (H_DIM / STRIPE_ROWS)          // 8
#define RAW_ROWS 36                              // 32 + 2 halo each side
#define STR 260                                  // row stride floats (1040B)
#define CH_OFF (RAW_ROWS * STR)                  // 9360 floats per channel
#define CG 2
#define SMEM_BYTES (CG * CH_OFF * 4)             // 74880
#define TX_BYTES (CG * RAW_ROWS * W_DIM * 4)     // 73728
#define FIRSTWAVE 444                            // 148 SMs x 3 blocks/SM
#define STAGGER_NS 2000ULL
#define KPT 16                                   // keypoints per thread

static __device__ __forceinline__ float gval(float i) {
    float d = i - 2.0f;
    return __expf(-d * d * 0.125f);              // exp(-d^2/(2*sigma^2))
}

static __device__ __forceinline__ uint32_t smem_u32(const void* p) {
    return (uint32_t)__cvta_generic_to_shared(p);
}

static __device__ __forceinline__ unsigned long long gtimer() {
    unsigned long long v;
    asm volatile("mov.u64 %0, %%globaltimer;" : "=l"(v));
    return v;
}

__global__ void __launch_bounds__(256, 3)
gauss_pool_kernel(const float* __restrict__ fm,
                  const int* __restrict__ kp32,
                  float* __restrict__ out)
{
    extern __shared__ float s_v[];               // raw -> in-place V tiles
    __shared__ __align__(16) float s_gx[4][8];
    __shared__ __align__(8)  unsigned long long s_mbar;
    __shared__ int s_flag;                       // kp dtype: nonzero => int32
    __shared__ int s_cnt;                        // queue count

    const int cg0    = (blockIdx.x & 255) * CG;
    const int stripe = blockIdx.x >> 8;
    const int t      = threadIdx.x;
    const int row0   = stripe * STRIPE_ROWS - 2;

    const uint32_t mbar = smem_u32(&s_mbar);

    if (t == 0) {
        asm volatile("mbarrier.init.shared.b64 [%0], %1;"
                     :: "r"(mbar), "r"(1u) : "memory");
        s_cnt = 0;
    }
    // dtype detect: odd int32 words are y coords (int32 case; 32 random
    // values in [0,256) can't all be 0) or int64 high halves (all zero).
    if (t < 32) {
        int v = kp32[2 * t + 1];
        v = __reduce_or_sync(0xffffffffu, v);
        if (t == 0) s_flag = v;
    }

    // ---- phase stagger: de-phase-lock co-resident blocks' fetch bursts ----
    if (t == 0 && blockIdx.x < FIRSTWAVE) {
        const unsigned long long delay =
            (unsigned long long)(blockIdx.x % 3) * STAGGER_NS;
        if (delay) {
            const unsigned long long tgt = gtimer() + delay;
            int guard = 0;
            while (gtimer() < tgt && ++guard < 1000000) __nanosleep(128);
        }
    }
    __syncthreads();                             // mbar + flag + stagger

    if (t == 0) {
        asm volatile("mbarrier.arrive.expect_tx.shared.b64 _, [%0], %1;"
                     :: "r"(mbar), "r"((uint32_t)TX_BYTES) : "memory");
    }
    // 72 bulk copies: 2 channels x 36 rows, 1KB each (TMA engine).
    if (t < CG * RAW_ROWS) {
        const int ch  = t / RAW_ROWS;
        const int row = t - ch * RAW_ROWS;
        const int gr  = min(max(row0 + row, 0), H_DIM - 1);  // legal addr;
        // clamped rows are never read (keypoint y clipped to [2,253])
        const float* src = fm + (size_t)(cg0 + ch) * PLANE + gr * W_DIM;
        const uint32_t dst =
            smem_u32(s_v) + (uint32_t)(ch * CH_OFF + row * STR) * 4u;
        asm volatile(
            "cp.async.bulk.shared::cta.global.mbarrier::complete_tx::bytes "
            "[%0], [%1], %2, [%3];"
            :: "r"(dst), "l"(src), "r"((uint32_t)(W_DIM * 4)), "r"(mbar)
            : "memory");
    }

    // ---- scan ALL keypoints while the fetch is in flight ----
    // thread handles kps n = t + 256*i; clipped coords packed 16-bit.
    unsigned pk[KPT / 2];
    if (s_flag) {                                // int32 pairs
        const int2* kp2 = (const int2*)kp32;
        #pragma unroll
        for (int i = 0; i < KPT; ++i) {
            int2 v = kp2[t + 256 * i];
            int x = min(max(v.x, 2), W_DIM - 3);
            int y = min(max(v.y, 2), H_DIM - 3);
            unsigned h = (unsigned)((x << 8) | y);
            if (i & 1) pk[i >> 1] |= h << 16; else pk[i >> 1] = h;
        }
    } else {                                     // int64 pairs (LE)
        const int4* kp4 = (const int4*)kp32;
        #pragma unroll
        for (int i = 0; i < KPT; ++i) {
            int4 v = kp4[t + 256 * i];
            int x = min(max(v.x, 2), W_DIM - 3);
            int y = min(max(v.z, 2), H_DIM - 3);
            unsigned h = (unsigned)((x << 8) | y);
            if (i & 1) pk[i >> 1] |= h << 16; else pk[i >> 1] = h;
        }
    }

    const float inv_norm =
        1.0f / (gval(0.f) + gval(1.f) + gval(2.f) + gval(3.f) + gval(4.f));

    if (t < 32) {
        int off = t >> 3, j = t & 7;
        int i = j - off;
        s_gx[off][j] = (i >= 0 && i < 5) ? gval((float)i) * inv_norm : 0.0f;
    }

    const float g0 = gval(0.f) * inv_norm;
    const float g1 = gval(1.f) * inv_norm;
    const float g2 = gval(2.f) * inv_norm;

    // wait for the raw tile (parity 0; acquire orders subsequent LDS)
    {
        uint32_t done;
        asm volatile(
            "{\n\t.reg .pred p;\n\t"
            "mbarrier.try_wait.parity.acquire.cta.shared::cta.b64 p, [%1], %2;\n\t"
            "selp.b32 %0, 1, 0, p;\n\t}"
            : "=r"(done) : "r"(mbar), "r"(0u) : "memory");
        if (!done) {
            asm volatile(
                "{\n\t.reg .pred P1;\n\t"
                "W_%=:\n\t"
                "mbarrier.try_wait.parity.acquire.cta.shared::cta.b64 P1, [%0], %1, 0x989680;\n\t"
                "@P1 bra.uni D_%=;\n\t"
                "bra.uni W_%=;\n\t"
                "D_%=:\n\t}"
                :: "r"(mbar), "r"(0u) : "memory");
        }
    }

    // ---- vertical conv SMEM->SMEM, in place, sync-free regions ----
    // Thread owns (ch, half, float4-column); rolling 5-reg window writes V
    // row k over raw row k after raw k..k+4 staged. Half 0 preloads raw
    // rows 16..19 (overwritten by half 1) before the single barrier.
    {
        const int strip = t & 63;                // float4 column 0..63
        const int ch    = (t >> 6) & 1;
        const int half  = t >> 7;                // 0: V rows 0..15, 1: 16..31
        float* tile = s_v + ch * CH_OFF;
        const int r0 = half * 16;

        float4 sv16, sv17, sv18, sv19;
        if (half == 0) {
            sv16 = *(const float4*)&tile[16 * STR + strip * 4];
            sv17 = *(const float4*)&tile[17 * STR + strip * 4];
            sv18 = *(const float4*)&tile[18 * STR + strip * 4];
            sv19 = *(const float4*)&tile[19 * STR + strip * 4];
        }
        __syncthreads();                         // preloads before h1 writes

        float4 w0, w1, w2, w3, w4;
        w1 = *(const float4*)&tile[(r0 + 0) * STR + strip * 4];
        w2 = *(const float4*)&tile[(r0 + 1) * STR + strip * 4];
        w3 = *(const float4*)&tile[(r0 + 2) * STR + strip * 4];
        w4 = *(const float4*)&tile[(r0 + 3) * STR + strip * 4];

        #pragma unroll
        for (int k = 0; k < 16; ++k) {
            w0 = w1; w1 = w2; w2 = w3; w3 = w4;
            if (half == 0 && k >= 12) {          // warp-uniform branch
                w4 = (k == 12) ? sv16 : (k == 13) ? sv17
                   : (k == 14) ? sv18 : sv19;
            } else {
                w4 = *(const float4*)&tile[(r0 + k + 4) * STR + strip * 4];
            }
            float4 r;
            r.x = g0 * (w0.x + w4.x) + g1 * (w1.x + w3.x) + g2 * w2.x;
            r.y = g0 * (w0.y + w4.y) + g1 * (w1.y + w3.y) + g2 * w2.y;
            r.z = g0 * (w0.z + w4.z) + g1 * (w1.z + w3.z) + g2 * w2.z;
            r.w = g0 * (w0.w + w4.w) + g1 * (w1.w + w3.w) + g2 * w2.w;
            *(float4*)&tile[(r0 + k) * STR + strip * 4] = r;
        }
    }
    __syncthreads();                             // V done; halo rows now dead

    // ---- queue build into dead halo rows (V rows 32..35 unused) ----
    int* q = (int*)(s_v + CH_OFF + 32 * STR);    // 2080 ints >= max ~650
    const int lane = t & 31;
    #pragma unroll
    for (int i = 0; i < KPT; ++i) {
        const unsigned h = (pk[i >> 1] >> ((i & 1) * 16)) & 0xffffu;
        const int y = (int)(h & 255);
        const bool m = ((y >> 5) == stripe);
        const unsigned b = __ballot_sync(0xffffffffu, m);
        if (b) {
            const int nw = __popc(b);
            const int leader = __ffs(b) - 1;
            int base = 0;
            if (lane == leader) base = atomicAdd(&s_cnt, nw);
            base = __shfl_sync(0xffffffffu, base, leader);
            if (m) {
                const int pos = base + __popc(b & ((1u << lane) - 1u));
                const int n = t + 256 * i;
                q[pos] = (n << 16) | (int)h;
            }
        }
    }
    __syncthreads();
    const int cnt = s_cnt;

    // ---- gather: block-wide loop over the queue ----
    for (int i = t; i < cnt; i += 256) {
        const int v = q[i];
        const int y = v & 255;
        const int x = (v >> 8) & 255;
        const int n = v >> 16;

        const int w0c = x - 2;
        const int a   = w0c & ~3;
        const int off = w0c - a;
        const int yl  = y - stripe * STRIPE_ROWS;   // 0..31

        float4 G0 = *(const float4*)&s_gx[off][0];
        float4 G1 = *(const float4*)&s_gx[off][4];

        const float* b0 = s_v + yl * STR + a;
        const float* b1 = b0 + CH_OFF;

        float4 A = *(const float4*)(b0);
        float4 B = *(const float4*)(b0 + 4);
        float4 C = *(const float4*)(b1);
        float4 D = *(const float4*)(b1 + 4);

        float2 res;
        res.x = G0.x * A.x + G0.y * A.y + G0.z * A.z + G0.w * A.w
              + G1.x * B.x + G1.y * B.y + G1.z * B.z + G1.w * B.w;
        res.y = G0.x * C.x + G0.y * C.y + G0.z * C.z + G0.w * C.w
              + G1.x * D.x + G1.y * D.y + G1.z * D.z + G1.w * D.w;

        *(float2*)&out[n * C_DIM + cg0] = res;
    }
}

extern "C" void kernel_launch(void* const* d_in, const int* in_sizes, int n_in,
                              void* d_out, int out_size)
{
    const float* fm   = (const float*)d_in[0];
    const int*   kp32 = (const int*)d_in[1];
    float*       out  = (float*)d_out;

    cudaFuncSetAttribute(gauss_pool_kernel,
                         cudaFuncAttributeMaxDynamicSharedMemorySize,
                         SMEM_BYTES);

    gauss_pool_kernel<<<N_STRIPES * (C_DIM / CG), 256, SMEM_BYTES>>>(
        fm, kp32, out);
}

// round 16
// speedup vs baseline: 1.0179x; 1.0179x over previous
#include <cuda_runtime.h>
#include <cstdint>

// GaussianPooling: out[n,c] = sum_{dy,dx} fm[c, y+dy, x+dx] * kern[dy,dx]
// fm: [512,256,256] f32, keypoints: [4096,2] int (x,y), out: [4096,512] f32.
// Separable 5x5 Gaussian (sigma=2).
//
// SINGLE fused kernel. block = (stripe of 32 rows, channel pair), 3/SM:
//   - issue 72x cp.async.bulk row copies (TMA engine)
//   - while fetch is in flight: scan ALL keypoints (16/thread, coalesced,
//     L2-hot) into 8 packed registers
//   - mbarrier wait; sync-free in-place vertical conv (rolling 5-reg window)
//   - compact this stripe's matches into a smem queue overlaid on the dead
//     halo rows (ballot-aggregated atomics)
//   - block-wide gather: 2 LDS.128 per kp per channel, STG.64 out
// First-wave fetch stagger (2us steps) de-phase-locks DRAM bursts.

#define C_DIM 512
#define H_DIM 256
#define W_DIM 256
#define N_KP  4096
#define PLANE (H_DIM * W_DIM)
#define STRIPE_ROWS 32
#define N_STRIPES (H_DIM / STRIPE_ROWS)          // 8
#define RAW_ROWS 36                              // 32 + 2 halo each side
#define STR 260                                  // row stride floats (1040B)
#define CH_OFF (RAW_ROWS * STR)                  // 9360 floats per channel
#define CG 2
#define SMEM_BYTES (CG * CH_OFF * 4)             // 74880
#define TX_BYTES (CG * RAW_ROWS * W_DIM * 4)     // 73728
#define FIRSTWAVE 444                            // 148 SMs x 3 blocks/SM
#define STAGGER_NS 2000ULL
#define KPT 16                                   // keypoints per thread

static __device__ __forceinline__ float gval(float i) {
    float d = i - 2.0f;
    return __expf(-d * d * 0.125f);              // exp(-d^2/(2*sigma^2))
}

static __device__ __forceinline__ uint32_t smem_u32(const void* p) {
    return (uint32_t)__cvta_generic_to_shared(p);
}

static __device__ __forceinline__ unsigned long long gtimer() {
    unsigned long long v;
    asm volatile("mov.u64 %0, %%globaltimer;" : "=l"(v));
    return v;
}

__global__ void __launch_bounds__(256, 3)
gauss_pool_kernel(const float* __restrict__ fm,
                  const int* __restrict__ kp32,
                  float* __restrict__ out)
{
    extern __shared__ float s_v[];               // raw -> in-place V tiles
    __shared__ __align__(16) float s_gx[4][8];
    __shared__ __align__(8)  unsigned long long s_mbar;
    __shared__ int s_flag;                       // kp dtype: nonzero => int32
    __shared__ int s_cnt;                        // queue count

    const int cg0    = (blockIdx.x & 255) * CG;
    const int stripe = blockIdx.x >> 8;
    const int t      = threadIdx.x;
    const int row0   = stripe * STRIPE_ROWS - 2;

    const uint32_t mbar = smem_u32(&s_mbar);

    if (t == 0) {
        asm volatile("mbarrier.init.shared.b64 [%0], %1;"
                     :: "r"(mbar), "r"(1u) : "memory");
        s_cnt = 0;
    }
    // dtype detect: odd int32 words are y coords (int32 case; 32 random
    // values in [0,256) can't all be 0) or int64 high halves (all zero).
    if (t < 32) {
        int v = kp32[2 * t + 1];
        v = __reduce_or_sync(0xffffffffu, v);
        if (t == 0) s_flag = v;
    }

    // ---- phase stagger: de-phase-lock co-resident blocks' fetch bursts ----
    if (t == 0 && blockIdx.x < FIRSTWAVE) {
        const unsigned long long delay =
            (unsigned long long)(blockIdx.x % 3) * STAGGER_NS;
        if (delay) {
            const unsigned long long tgt = gtimer() + delay;
            int guard = 0;
            while (gtimer() < tgt && ++guard < 1000000) __nanosleep(128);
        }
    }
    __syncthreads();                             // mbar + flag + stagger

    if (t == 0) {
        asm volatile("mbarrier.arrive.expect_tx.shared.b64 _, [%0], %1;"
                     :: "r"(mbar), "r"((uint32_t)TX_BYTES) : "memory");
    }
    // 72 bulk copies: 2 channels x 36 rows, 1KB each (TMA engine).
    if (t < CG * RAW_ROWS) {
        const int ch  = t / RAW_ROWS;
        const int row = t - ch * RAW_ROWS;
        const int gr  = min(max(row0 + row, 0), H_DIM - 1);  // legal addr;
        // clamped rows are never read (keypoint y clipped to [2,253])
        const float* src = fm + (size_t)(cg0 + ch) * PLANE + gr * W_DIM;
        const uint32_t dst =
            smem_u32(s_v) + (uint32_t)(ch * CH_OFF + row * STR) * 4u;
        asm volatile(
            "cp.async.bulk.shared::cta.global.mbarrier::complete_tx::bytes "
            "[%0], [%1], %2, [%3];"
            :: "r"(dst), "l"(src), "r"((uint32_t)(W_DIM * 4)), "r"(mbar)
            : "memory");
    }

    // ---- scan ALL keypoints while the fetch is in flight ----
    // thread handles kps n = t + 256*i; clipped coords packed 16-bit.
    unsigned pk[KPT / 2];
    if (s_flag) {                                // int32 pairs
        const int2* kp2 = (const int2*)kp32;
        #pragma unroll
        for (int i = 0; i < KPT; ++i) {
            int2 v = kp2[t + 256 * i];
            int x = min(max(v.x, 2), W_DIM - 3);
            int y = min(max(v.y, 2), H_DIM - 3);
            unsigned h = (unsigned)((x << 8) | y);
            if (i & 1) pk[i >> 1] |= h << 16; else pk[i >> 1] = h;
        }
    } else {                                     // int64 pairs (LE)
        const int4* kp4 = (const int4*)kp32;
        #pragma unroll
        for (int i = 0; i < KPT; ++i) {
            int4 v = kp4[t + 256 * i];
            int x = min(max(v.x, 2), W_DIM - 3);
            int y = min(max(v.z, 2), H_DIM - 3);
            unsigned h = (unsigned)((x << 8) | y);
            if (i & 1) pk[i >> 1] |= h << 16; else pk[i >> 1] = h;
        }
    }

    const float inv_norm =
        1.0f / (gval(0.f) + gval(1.f) + gval(2.f) + gval(3.f) + gval(4.f));

    if (t < 32) {
        int off = t >> 3, j = t & 7;
        int i = j - off;
        s_gx[off][j] = (i >= 0 && i < 5) ? gval((float)i) * inv_norm : 0.0f;
    }

    const float g0 = gval(0.f) * inv_norm;
    const float g1 = gval(1.f) * inv_norm;
    const float g2 = gval(2.f) * inv_norm;

    // wait for the raw tile (parity 0; acquire orders subsequent LDS)
    {
        uint32_t done;
        asm volatile(
            "{\n\t.reg .pred p;\n\t"
            "mbarrier.try_wait.parity.acquire.cta.shared::cta.b64 p, [%1], %2;\n\t"
            "selp.b32 %0, 1, 0, p;\n\t}"
            : "=r"(done) : "r"(mbar), "r"(0u) : "memory");
        if (!done) {
            asm volatile(
                "{\n\t.reg .pred P1;\n\t"
                "W_%=:\n\t"
                "mbarrier.try_wait.parity.acquire.cta.shared::cta.b64 P1, [%0], %1, 0x989680;\n\t"
                "@P1 bra.uni D_%=;\n\t"
                "bra.uni W_%=;\n\t"
                "D_%=:\n\t}"
                :: "r"(mbar), "r"(0u) : "memory");
        }
    }

    // ---- vertical conv SMEM->SMEM, in place, sync-free regions ----
    // Thread owns (ch, half, float4-column); rolling 5-reg window writes V
    // row k over raw row k after raw k..k+4 staged. Half 0 preloads raw
    // rows 16..19 (overwritten by half 1) before the single barrier.
    {
        const int strip = t & 63;                // float4 column 0..63
        const int ch    = (t >> 6) & 1;
        const int half  = t >> 7;                // 0: V rows 0..15, 1: 16..31
        float* tile = s_v + ch * CH_OFF;
        const int r0 = half * 16;

        float4 sv16, sv17, sv18, sv19;
        if (half == 0) {
            sv16 = *(const float4*)&tile[16 * STR + strip * 4];
            sv17 = *(const float4*)&tile[17 * STR + strip * 4];
            sv18 = *(const float4*)&tile[18 * STR + strip * 4];
            sv19 = *(const float4*)&tile[19 * STR + strip * 4];
        }
        __syncthreads();                         // preloads before h1 writes

        float4 w0, w1, w2, w3, w4;
        w1 = *(const float4*)&tile[(r0 + 0) * STR + strip * 4];
        w2 = *(const float4*)&tile[(r0 + 1) * STR + strip * 4];
        w3 = *(const float4*)&tile[(r0 + 2) * STR + strip * 4];
        w4 = *(const float4*)&tile[(r0 + 3) * STR + strip * 4];

        #pragma unroll
        for (int k = 0; k < 16; ++k) {
            w0 = w1; w1 = w2; w2 = w3; w3 = w4;
            if (half == 0 && k >= 12) {          // warp-uniform branch
                w4 = (k == 12) ? sv16 : (k == 13) ? sv17
                   : (k == 14) ? sv18 : sv19;
            } else {
                w4 = *(const float4*)&tile[(r0 + k + 4) * STR + strip * 4];
            }
            float4 r;
            r.x = g0 * (w0.x + w4.x) + g1 * (w1.x + w3.x) + g2 * w2.x;
            r.y = g0 * (w0.y + w4.y) + g1 * (w1.y + w3.y) + g2 * w2.y;
            r.z = g0 * (w0.z + w4.z) + g1 * (w1.z + w3.z) + g2 * w2.z;
            r.w = g0 * (w0.w + w4.w) + g1 * (w1.w + w3.w) + g2 * w2.w;
            *(float4*)&tile[(r0 + k) * STR + strip * 4] = r;
        }
    }
    __syncthreads();                             // V done; halo rows now dead

    // ---- queue build into dead halo rows (V rows 32..35 unused) ----
    int* q = (int*)(s_v + CH_OFF + 32 * STR);    // 2080 ints >= max ~650
    const int lane = t & 31;
    #pragma unroll
    for (int i = 0; i < KPT; ++i) {
        const unsigned h = (pk[i >> 1] >> ((i & 1) * 16)) & 0xffffu;
        const int y = (int)(h & 255);
        const bool m = ((y >> 5) == stripe);
        const unsigned b = __ballot_sync(0xffffffffu, m);
        if (b) {
            const int nw = __popc(b);
            const int leader = __ffs(b) - 1;
            int base = 0;
            if (lane == leader) base = atomicAdd(&s_cnt, nw);
            base = __shfl_sync(0xffffffffu, base, leader);
            if (m) {
                const int pos = base + __popc(b & ((1u << lane) - 1u));
                const int n = t + 256 * i;
                q[pos] = (n << 16) | (int)h;
            }
        }
    }
    __syncthreads();
    const int cnt = s_cnt;

    // ---- gather: block-wide loop over the queue ----
    for (int i = t; i < cnt; i += 256) {
        const int v = q[i];
        const int y = v & 255;
        const int x = (v >> 8) & 255;
        const int n = v >> 16;

        const int w0c = x - 2;
        const int a   = w0c & ~3;
        const int off = w0c - a;
        const int yl  = y - stripe * STRIPE_ROWS;   // 0..31

        float4 G0 = *(const float4*)&s_gx[off][0];
        float4 G1 = *(const float4*)&s_gx[off][4];

        const float* b0 = s_v + yl * STR + a;
        const float* b1 = b0 + CH_OFF;

        float4 A = *(const float4*)(b0);
        float4 B = *(const float4*)(b0 + 4);
        float4 C = *(const float4*)(b1);
        float4 D = *(const float4*)(b1 + 4);

        float2 res;
        res.x = G0.x * A.x + G0.y * A.y + G0.z * A.z + G0.w * A.w
              + G1.x * B.x + G1.y * B.y + G1.z * B.z + G1.w * B.w;
        res.y = G0.x * C.x + G0.y * C.y + G0.z * C.z + G0.w * C.w
              + G1.x * D.x + G1.y * D.y + G1.z * D.z + G1.w * D.w;

        *(float2*)&out[n * C_DIM + cg0] = res;
    }
}

extern "C" void kernel_launch(void* const* d_in, const int* in_sizes, int n_in,
                              void* d_out, int out_size)
{
    const float* fm   = (const float*)d_in[0];
    const int*   kp32 = (const int*)d_in[1];
    float*       out  = (float*)d_out;

    cudaFuncSetAttribute(gauss_pool_kernel,
                         cudaFuncAttributeMaxDynamicSharedMemorySize,
                         SMEM_BYTES);

    gauss_pool_kernel<<<N_STRIPES * (C_DIM / CG), 256, SMEM_BYTES>>>(
        fm, kp32, out);
}

// round 17
// speedup vs baseline: 1.3168x; 1.2937x over previous
#include <cuda_runtime.h>
#include <cstdint>

// GaussianPooling: out[n,c] = sum_{dy,dx} fm[c, y+dy, x+dx] * kern[dy,dx]
// fm: [512,256,256] f32, keypoints: [4096,2] int (x,y), out: [4096,512] f32.
// Separable 5x5 Gaussian (sigma=2).
//
// prep (128 blocks, PDL early-trigger) bins keypoints into 8 stripe x 16
// part queues. main: block = (32-row stripe, channel pair), 3/SM:
// TMA bulk-copy tile -> sync-free in-place vertical conv -> warp-per-part
// gather (2 LDS.128 per kp per channel, STG.64 out). First-wave 2us fetch
// stagger de-phase-locks DRAM bursts (R13-validated).

#define C_DIM 512
#define H_DIM 256
#define W_DIM 256
#define N_KP  4096
#define PLANE (H_DIM * W_DIM)
#define STRIPE_ROWS 32
#define N_STRIPES (H_DIM / STRIPE_ROWS)          // 8
#define N_PARTS 16
#define PART_KP (N_KP / N_PARTS)                 // 256
#define RAW_ROWS 36                              // 32 + 2 halo each side
#define STR 260                                  // row stride floats (1040B)
#define CH_OFF (RAW_ROWS * STR)                  // 9360 floats per channel
#define CG 2
#define SMEM_BYTES (CG * CH_OFF * 4)             // 74880
#define TX_BYTES (CG * RAW_ROWS * W_DIM * 4)     // 73728
#define FIRSTWAVE 444                            // 148 SMs x 3 blocks/SM
#define STAGGER_NS 2000ULL                       // R13-validated value

__device__ int g_q[N_STRIPES * N_PARTS * PART_KP];  // packed (n<<16)|(x<<8)|y
__device__ int g_qcnt[N_STRIPES * N_PARTS];

static __device__ __forceinline__ float gval(float i) {
    float d = i - 2.0f;
    return __expf(-d * d * 0.125f);              // exp(-d^2/(2*sigma^2))
}

static __device__ __forceinline__ uint32_t smem_u32(const void* p) {
    return (uint32_t)__cvta_generic_to_shared(p);
}

static __device__ __forceinline__ unsigned long long gtimer() {
    unsigned long long v;
    asm volatile("mov.u64 %0, %%globaltimer;" : "=l"(v));
    return v;
}

// grid = 8 stripes x 16 parts. Each block scans its 256-keypoint slice for
// its stripe. dtype detect per slice: words kp32[2n+1] are y (int32 case,
// random nonzero somewhere in slice) or int64 high halves (all zero).
__global__ void prep_kp_kernel(const int* __restrict__ kp32)
{
    __shared__ int s_or[256];
    __shared__ int s_flag;
    __shared__ int s_cnt;
    const int t      = threadIdx.x;
    const int stripe = blockIdx.x >> 4;
    const int part   = blockIdx.x & (N_PARTS - 1);
    const int n      = part * PART_KP + t;

    s_or[t] = kp32[2 * n + 1];
    if (t == 0) s_cnt = 0;
    __syncthreads();
    for (int s = 128; s > 0; s >>= 1) {
        if (t < s) s_or[t] |= s_or[t + s];
        __syncthreads();
    }
    if (t == 0) s_flag = s_or[0];
    __syncthreads();
    const bool is_i32 = (s_flag != 0);

    int x, y;
    if (is_i32) { x = kp32[2 * n];     y = kp32[2 * n + 1]; }
    else        { x = kp32[4 * n];     y = kp32[4 * n + 2]; }
    x = min(max(x, 2), W_DIM - 3);
    y = min(max(y, 2), H_DIM - 3);

    if ((y >> 5) == stripe) {
        int idx = atomicAdd(&s_cnt, 1);
        g_q[(stripe * N_PARTS + part) * PART_KP + idx] =
            (n << 16) | (x << 8) | y;
    }
    __syncthreads();
    if (t == 0) g_qcnt[stripe * N_PARTS + part] = s_cnt;

    cudaTriggerProgrammaticLaunchCompletion();
}

__global__ void __launch_bounds__(256, 3)
gauss_pool_kernel(const float* __restrict__ fm, float* __restrict__ out)
{
    extern __shared__ float s_v[];               // raw then in-place V tiles
    __shared__ __align__(16) float s_gx[4][8];
    __shared__ __align__(8)  unsigned long long s_mbar;

    const int cg0    = (blockIdx.x & 255) * CG;
    const int stripe = blockIdx.x >> 8;
    const int t      = threadIdx.x;
    const int row0   = stripe * STRIPE_ROWS - 2;

    const uint32_t mbar = smem_u32(&s_mbar);

    if (t == 0) {
        asm volatile("mbarrier.init.shared.b64 [%0], %1;"
                     :: "r"(mbar), "r"(1u) : "memory");
    }

    // ---- phase stagger: de-phase-lock co-resident blocks' fetch bursts ----
    if (t == 0 && blockIdx.x < FIRSTWAVE) {
        const unsigned long long delay =
            (unsigned long long)(blockIdx.x % 3) * STAGGER_NS;
        if (delay) {
            const unsigned long long tgt = gtimer() + delay;
            int guard = 0;
            while (gtimer() < tgt && ++guard < 1000000) __nanosleep(128);
        }
    }
    __syncthreads();                             // mbar init + stagger done

    if (t == 0) {
        asm volatile("mbarrier.arrive.expect_tx.shared.b64 _, [%0], %1;"
                     :: "r"(mbar), "r"((uint32_t)TX_BYTES) : "memory");
    }
    // 72 bulk copies: 2 channels x 36 rows, 1KB each (TMA engine).
    if (t < CG * RAW_ROWS) {
        const int ch  = t / RAW_ROWS;
        const int row = t - ch * RAW_ROWS;
        const int gr  = min(max(row0 + row, 0), H_DIM - 1);  // legal addr;
        // clamped rows are never read (keypoint y is clipped to [2,253])
        const float* src = fm + (size_t)(cg0 + ch) * PLANE + gr * W_DIM;
        const uint32_t dst =
            smem_u32(s_v) + (uint32_t)(ch * CH_OFF + row * STR) * 4u;
        asm volatile(
            "cp.async.bulk.shared::cta.global.mbarrier::complete_tx::bytes "
            "[%0], [%1], %2, [%3];"
            :: "r"(dst), "l"(src), "r"((uint32_t)(W_DIM * 4)), "r"(mbar)
            : "memory");
    }

    const float inv_norm =
        1.0f / (gval(0.f) + gval(1.f) + gval(2.f) + gval(3.f) + gval(4.f));

    if (t < 32) {
        int off = t >> 3, j = t & 7;
        int i = j - off;
        s_gx[off][j] = (i >= 0 && i < 5) ? gval((float)i) * inv_norm : 0.0f;
    }

    const float g0 = gval(0.f) * inv_norm;
    const float g1 = gval(1.f) * inv_norm;
    const float g2 = gval(2.f) * inv_norm;

    // wait for the raw tile (parity 0; acquire orders subsequent LDS)
    {
        uint32_t done;
        asm volatile(
            "{\n\t.reg .pred p;\n\t"
            "mbarrier.try_wait.parity.acquire.cta.shared::cta.b64 p, [%1], %2;\n\t"
            "selp.b32 %0, 1, 0, p;\n\t}"
            : "=r"(done) : "r"(mbar), "r"(0u) : "memory");
        if (!done) {
            asm volatile(
                "{\n\t.reg .pred P1;\n\t"
                "W_%=:\n\t"
                "mbarrier.try_wait.parity.acquire.cta.shared::cta.b64 P1, [%0], %1, 0x989680;\n\t"
                "@P1 bra.uni D_%=;\n\t"
                "bra.uni W_%=;\n\t"
                "D_%=:\n\t}"
                :: "r"(mbar), "r"(0u) : "memory");
        }
    }

    // ---- vertical conv SMEM->SMEM, in place, sync-free regions ----
    // Thread owns (ch, half, float4-column); rolling 5-reg window writes V
    // row k over raw row k after raw rows k..k+4 are staged. Cross-thread
    // hazard: half 0 reads raw rows 16..19 which half 1 overwrites ->
    // half 0 preloads them before the single barrier.
    {
        const int strip = t & 63;                // float4 column 0..63
        const int ch    = (t >> 6) & 1;          // channel within pair
        const int half  = t >> 7;                // 0: V rows 0..15, 1: 16..31
        float* tile = s_v + ch * CH_OFF;
        const int r0 = half * 16;

        float4 sv16, sv17, sv18, sv19;
        if (half == 0) {                         // boundary rows, pre-barrier
            sv16 = *(const float4*)&tile[16 * STR + strip * 4];
            sv17 = *(const float4*)&tile[17 * STR + strip * 4];
            sv18 = *(const float4*)&tile[18 * STR + strip * 4];
            sv19 = *(const float4*)&tile[19 * STR + strip * 4];
        }
        __syncthreads();                         // preloads before h1 writes

        float4 w0, w1, w2, w3, w4;
        w1 = *(const float4*)&tile[(r0 + 0) * STR + strip * 4];
        w2 = *(const float4*)&tile[(r0 + 1) * STR + strip * 4];
        w3 = *(const float4*)&tile[(r0 + 2) * STR + strip * 4];
        w4 = *(const float4*)&tile[(r0 + 3) * STR + strip * 4];

        #pragma unroll
        for (int k = 0; k < 16; ++k) {
            w0 = w1; w1 = w2; w2 = w3; w3 = w4;
            if (half == 0 && k >= 12) {          // warp-uniform branch
                w4 = (k == 12) ? sv16 : (k == 13) ? sv17
                   : (k == 14) ? sv18 : sv19;
            } else {
                w4 = *(const float4*)&tile[(r0 + k + 4) * STR + strip * 4];
            }
            float4 r;
            r.x = g0 * (w0.x + w4.x) + g1 * (w1.x + w3.x) + g2 * w2.x;
            r.y = g0 * (w0.y + w4.y) + g1 * (w1.y + w3.y) + g2 * w2.y;
            r.z = g0 * (w0.z + w4.z) + g1 * (w1.z + w3.z) + g2 * w2.z;
            r.w = g0 * (w0.w + w4.w) + g1 * (w1.w + w3.w) + g2 * w2.w;
            *(float4*)&tile[(r0 + k) * STR + strip * 4] = r;
        }
    }
    __syncthreads();                             // V visible to gather

    cudaGridDependencySynchronize();             // queues ready (PDL)

    // ---- Phase 2: one warp per part (16 parts, 8 warps x 2 rounds) ----
    const int warp = t >> 5;
    const int lane = t & 31;

    #pragma unroll 1
    for (int pp = 0; pp < N_PARTS / 8; ++pp) {
        const int p   = warp + pp * 8;
        const int qi  = stripe * N_PARTS + p;
        const int cnt = g_qcnt[qi];
        const int* q  = &g_q[qi * PART_KP];

        for (int i = lane; i < cnt; i += 32) {
            const int v = q[i];
            const int y = v & 255;
            const int x = (v >> 8) & 255;
            const int n = v >> 16;

            const int w0c = x - 2;
            const int a   = w0c & ~3;
            const int off = w0c - a;
            const int yl  = y - stripe * STRIPE_ROWS;   // 0..31

            float4 G0 = *(const float4*)&s_gx[off][0];
            float4 G1 = *(const float4*)&s_gx[off][4];

            const float* b0 = s_v + yl * STR + a;
            const float* b1 = b0 + CH_OFF;

            float4 A = *(const float4*)(b0);
            float4 B = *(const float4*)(b0 + 4);
            float4 C = *(const float4*)(b1);
            float4 D = *(const float4*)(b1 + 4);

            float2 res;
            res.x = G0.x * A.x + G0.y * A.y + G0.z * A.z + G0.w * A.w
                  + G1.x * B.x + G1.y * B.y + G1.z * B.z + G1.w * B.w;
            res.y = G0.x * C.x + G0.y * C.y + G0.z * C.z + G0.w * C.w
                  + G1.x * D.x + G1.y * D.y + G1.z * D.z + G1.w * D.w;

            *(float2*)&out[n * C_DIM + cg0] = res;
        }
    }
}

extern "C" void kernel_launch(void* const* d_in, const int* in_sizes, int n_in,
                              void* d_out, int out_size)
{
    const float* fm   = (const float*)d_in[0];
    const int*   kp32 = (const int*)d_in[1];
    float*       out  = (float*)d_out;

    cudaFuncSetAttribute(gauss_pool_kernel,
                         cudaFuncAttributeMaxDynamicSharedMemorySize,
                         SMEM_BYTES);

    prep_kp_kernel<<<N_STRIPES * N_PARTS, 256>>>(kp32);

    cudaLaunchConfig_t cfg = {};
    cfg.gridDim  = dim3(N_STRIPES * (C_DIM / CG));
    cfg.blockDim = dim3(256);
    cfg.dynamicSmemBytes = SMEM_BYTES;
    cfg.stream = 0;
    cudaLaunchAttribute attr[1];
    attr[0].id = cudaLaunchAttributeProgrammaticStreamSerialization;
    attr[0].val.programmaticStreamSerializationAllowed = 1;
    cfg.attrs = attr;
    cfg.numAttrs = 1;
    cudaLaunchKernelEx(&cfg, gauss_pool_kernel, fm, out);
}